// round 7
// baseline (speedup 1.0000x reference)
#include <cuda_runtime.h>
#include <cuda_bf16.h>

#define BB 8
#define FF 16384
#define HH 256
#define NROWS (BB*FF)
#define CHUNK 256
#define NCHB  (FF/CHUNK)        // 64 chunks per batch
#define NCHT  (BB*NCHB)         // 512 chunks total

typedef unsigned long long u64;

// ---------------- scratch (__device__ globals; no allocation) ----------------
__device__ float4 g_dq[NROWS];        // per-row delta quaternion
__device__ float4 g_pq[NROWS];        // within-chunk inclusive quat prefix
__device__ float4 g_cq[NCHT];         // per-chunk quat product
__device__ float4 g_cpre[NCHT];       // per-chunk exclusive quat prefix (incl q0)
__device__ float  g_cacc[NROWS*3];    // corrected acc
__device__ float  g_eTSC[7*(size_t)NROWS]; // SoA within-chunk inclusive TSC
__device__ float  g_cTSC[NCHT*7];     // per-chunk TSC summary
__device__ float  g_cstart[NCHT*6];   // per-chunk (pos,vel) start state
__device__ unsigned int g_ctr1 = 0;
__device__ unsigned int g_ctr2 = 0;

// ---------------- packed f32x2 helpers ----------------
__device__ __forceinline__ u64 pk2(float lo, float hi) {
    u64 r; asm("mov.b64 %0,{%1,%2};" : "=l"(r) : "f"(lo), "f"(hi)); return r;
}
__device__ __forceinline__ void upk2(u64 v, float& lo, float& hi) {
    asm("mov.b64 {%0,%1},%2;" : "=f"(lo), "=f"(hi) : "l"(v));
}
__device__ __forceinline__ u64 ffma2(u64 a, u64 b, u64 c) {
    u64 r; asm("fma.rn.f32x2 %0,%1,%2,%3;" : "=l"(r) : "l"(a), "l"(b), "l"(c)); return r;
}
__device__ __forceinline__ u64 fmul2(u64 a, u64 b) {
    u64 r; asm("mul.rn.f32x2 %0,%1,%2;" : "=l"(r) : "l"(a), "l"(b)); return r;
}
__device__ __forceinline__ float tanha(float x) {
    float r; asm("tanh.approx.f32 %0,%1;" : "=f"(r) : "f"(x)); return r;
}

// quaternion as float4: .x=w, .y..w = vector
__device__ __forceinline__ float4 qmul(float4 q, float4 p) {
    float4 r;
    r.x = q.x*p.x - q.y*p.y - q.z*p.z - q.w*p.w;
    r.y = q.x*p.y + p.x*q.y + (q.z*p.w - q.w*p.z);
    r.z = q.x*p.z + p.x*q.z + (q.w*p.y - q.y*p.w);
    r.w = q.x*p.w + p.x*q.w + (q.y*p.z - q.z*p.y);
    return r;
}

__device__ __forceinline__ float4 shfl_up_q(float4 v, int off) {
    float4 r;
    r.x = __shfl_up_sync(0xffffffffu, v.x, off);
    r.y = __shfl_up_sync(0xffffffffu, v.y, off);
    r.z = __shfl_up_sync(0xffffffffu, v.z, off);
    r.w = __shfl_up_sync(0xffffffffu, v.w, off);
    return r;
}

struct TSC { float T, S0, S1, S2, C0, C1, C2; };
__device__ __forceinline__ TSC tsc_comb(const TSC& l, const TSC& r) {
    TSC o;
    o.C0 = l.C0 + r.C0 + l.S0*r.T;
    o.C1 = l.C1 + r.C1 + l.S1*r.T;
    o.C2 = l.C2 + r.C2 + l.S2*r.T;
    o.S0 = l.S0 + r.S0; o.S1 = l.S1 + r.S1; o.S2 = l.S2 + r.S2;
    o.T  = l.T + r.T;
    return o;
}
__device__ __forceinline__ TSC shfl_up_tsc(const TSC& v, int off) {
    TSC r;
    r.T  = __shfl_up_sync(0xffffffffu, v.T, off);
    r.S0 = __shfl_up_sync(0xffffffffu, v.S0, off);
    r.S1 = __shfl_up_sync(0xffffffffu, v.S1, off);
    r.S2 = __shfl_up_sync(0xffffffffu, v.S2, off);
    r.C0 = __shfl_up_sync(0xffffffffu, v.C0, off);
    r.C1 = __shfl_up_sync(0xffffffffu, v.C1, off);
    r.C2 = __shfl_up_sync(0xffffffffu, v.C2, off);
    return r;
}

// per-row tail: corrections -> out, cacc, delta quat -> g_dq
__device__ __forceinline__ void row_tail(
    int r, float c0, float c1, float c2, float c3, float c4, float c5,
    float x0, float x1, float x2, float x3, float x4, float x5,
    const float* __restrict__ dt, float* __restrict__ out)
{
    size_t ob = (size_t)r * 16;
    out[ob+10] = c0; out[ob+11] = c1; out[ob+12] = c2;
    out[ob+13] = c3; out[ob+14] = c4; out[ob+15] = c5;
    g_cacc[r*3+0] = c0 + x0;
    g_cacc[r*3+1] = c1 + x1;
    g_cacc[r*3+2] = c2 + x2;
    float dtv = dt[r];
    float v0 = (c3 + x3) * dtv;
    float v1 = (c4 + x4) * dtv;
    float v2 = (c5 + x5) * dtv;
    float tt2 = v0*v0 + v1*v1 + v2*v2;
    float theta = sqrtf(tt2 + 1e-16f);
    float half  = 0.5f * theta;
    float w  = cosf(half);
    float sc = (tt2 < 1e-12f) ? (0.5f - tt2 * (1.0f/48.0f)) : (sinf(half) / theta);
    g_dq[r] = make_float4(w, v0*sc, v1*sc, v2*sc);
}

// ---------------------------------------------------------------------------
// K1: MLP only. 2 rows/thread. 64-thread blocks so the full grid is resident
//     in one wave (no quantization) with ~26 warps/SM of latency hiding.
// grid = 1024 blocks of 64 threads; block handles rows [blk*128, blk*128+128)
// ---------------------------------------------------------------------------
__global__ void __launch_bounds__(64)
mlp_kernel(const float* __restrict__ acc, const float* __restrict__ gyro,
           const float* __restrict__ dt,
           const float* __restrict__ W_enc, const float* __restrict__ b_enc,
           const float* __restrict__ W_dec, const float* __restrict__ b_dec,
           float* __restrict__ out)
{
    __shared__ __align__(16) u64 s_w[128*16];
    int tid = threadIdx.x;

    #pragma unroll
    for (int pp = 0; pp < 2; pp++) {
        int p = tid + pp*64;
        #pragma unroll
        for (int k = 0; k < 6; k++) {
            const float2 v = reinterpret_cast<const float2*>(W_enc + k*HH)[p];
            s_w[p*16 + k] = pk2(v.x, v.y);
        }
        const float2 bb = reinterpret_cast<const float2*>(b_enc)[p];
        s_w[p*16 + 6] = pk2(bb.x, bb.y);
        #pragma unroll
        for (int k = 0; k < 6; k++) {
            s_w[p*16 + 7 + k] = pk2(W_dec[(2*p)*6 + k], W_dec[(2*p+1)*6 + k]);
        }
        s_w[p*16 + 13] = 0; s_w[p*16 + 14] = 0; s_w[p*16 + 15] = 0;
    }
    __syncthreads();

    int rA = blockIdx.x * 128 + tid;
    int rB = rA + 64;
    float xA0 = acc[rA*3+0], xA1 = acc[rA*3+1], xA2 = acc[rA*3+2];
    float xA3 = gyro[rA*3+0], xA4 = gyro[rA*3+1], xA5 = gyro[rA*3+2];
    float xB0 = acc[rB*3+0], xB1 = acc[rB*3+1], xB2 = acc[rB*3+2];
    float xB3 = gyro[rB*3+0], xB4 = gyro[rB*3+1], xB5 = gyro[rB*3+2];
    u64 XA0 = pk2(xA0,xA0), XA1 = pk2(xA1,xA1), XA2 = pk2(xA2,xA2);
    u64 XA3 = pk2(xA3,xA3), XA4 = pk2(xA4,xA4), XA5 = pk2(xA5,xA5);
    u64 XB0 = pk2(xB0,xB0), XB1 = pk2(xB1,xB1), XB2 = pk2(xB2,xB2);
    u64 XB3 = pk2(xB3,xB3), XB4 = pk2(xB4,xB4), XB5 = pk2(xB5,xB5);

    u64 CU1 = pk2(0.7978845608028654f, 0.7978845608028654f);
    u64 CU3 = pk2(0.035677408136300125f, 0.035677408136300125f);
    u64 HLF = pk2(0.5f, 0.5f);

    u64 aA0=0,aA1=0,aA2=0,aA3=0,aA4=0,aA5=0;
    u64 aB0=0,aB1=0,aB2=0,aB3=0,aB4=0,aB5=0;

    #pragma unroll 2
    for (int p = 0; p < 128; p++) {
        const ulonglong2* q = reinterpret_cast<const ulonglong2*>(s_w + p*16);
        ulonglong2 q0 = q[0], q1 = q[1], q2 = q[2], q3 = q[3], q4 = q[4], q5 = q[5];
        u64 dec5 = reinterpret_cast<const u64*>(s_w + p*16)[12];

        u64 preA = q3.x, preB = q3.x;
        preA = ffma2(q0.x, XA0, preA);  preB = ffma2(q0.x, XB0, preB);
        preA = ffma2(q0.y, XA1, preA);  preB = ffma2(q0.y, XB1, preB);
        preA = ffma2(q1.x, XA2, preA);  preB = ffma2(q1.x, XB2, preB);
        preA = ffma2(q1.y, XA3, preA);  preB = ffma2(q1.y, XB3, preB);
        preA = ffma2(q2.x, XA4, preA);  preB = ffma2(q2.x, XB4, preB);
        preA = ffma2(q2.y, XA5, preA);  preB = ffma2(q2.y, XB5, preB);

        u64 s2A = fmul2(preA, preA);    u64 s2B = fmul2(preB, preB);
        u64 t2A = ffma2(s2A, CU3, CU1); u64 t2B = ffma2(s2B, CU3, CU1);
        u64 upA = fmul2(preA, t2A);     u64 upB = fmul2(preB, t2B);
        float uA0, uA1, uB0, uB1;
        upk2(upA, uA0, uA1); upk2(upB, uB0, uB1);
        u64 thA = pk2(tanha(uA0), tanha(uA1));
        u64 thB = pk2(tanha(uB0), tanha(uB1));
        u64 omA = ffma2(thA, HLF, HLF); u64 omB = ffma2(thB, HLF, HLF);
        u64 ftA = fmul2(preA, omA);     u64 ftB = fmul2(preB, omB);

        aA0 = ffma2(ftA, q3.y, aA0);    aB0 = ffma2(ftB, q3.y, aB0);
        aA1 = ffma2(ftA, q4.x, aA1);    aB1 = ffma2(ftB, q4.x, aB1);
        aA2 = ffma2(ftA, q4.y, aA2);    aB2 = ffma2(ftB, q4.y, aB2);
        aA3 = ffma2(ftA, q5.x, aA3);    aB3 = ffma2(ftB, q5.x, aB3);
        aA4 = ffma2(ftA, q5.y, aA4);    aB4 = ffma2(ftB, q5.y, aB4);
        aA5 = ffma2(ftA, dec5, aA5);    aB5 = ffma2(ftB, dec5, aB5);
    }

    float bd0 = __ldg(&b_dec[0]), bd1 = __ldg(&b_dec[1]), bd2 = __ldg(&b_dec[2]);
    float bd3 = __ldg(&b_dec[3]), bd4 = __ldg(&b_dec[4]), bd5 = __ldg(&b_dec[5]);
    float lo, hi;
    float cA0, cA1, cA2, cA3, cA4, cA5, cB0, cB1, cB2, cB3, cB4, cB5;
    upk2(aA0, lo, hi); cA0 = lo + hi + bd0;
    upk2(aA1, lo, hi); cA1 = lo + hi + bd1;
    upk2(aA2, lo, hi); cA2 = lo + hi + bd2;
    upk2(aA3, lo, hi); cA3 = lo + hi + bd3;
    upk2(aA4, lo, hi); cA4 = lo + hi + bd4;
    upk2(aA5, lo, hi); cA5 = lo + hi + bd5;
    upk2(aB0, lo, hi); cB0 = lo + hi + bd0;
    upk2(aB1, lo, hi); cB1 = lo + hi + bd1;
    upk2(aB2, lo, hi); cB2 = lo + hi + bd2;
    upk2(aB3, lo, hi); cB3 = lo + hi + bd3;
    upk2(aB4, lo, hi); cB4 = lo + hi + bd4;
    upk2(aB5, lo, hi); cB5 = lo + hi + bd5;

    row_tail(rA, cA0,cA1,cA2,cA3,cA4,cA5, xA0,xA1,xA2,xA3,xA4,xA5, dt, out);
    row_tail(rB, cB0,cB1,cB2,cB3,cB4,cB5, xB0,xB1,xB2,xB3,xB4,xB5, dt, out);
}

// ---------------------------------------------------------------------------
// K1b: within-chunk quat scan + last-block cross-chunk exclusive prefix
// grid = 512 (chunk), block = 256
// ---------------------------------------------------------------------------
__global__ void __launch_bounds__(256)
chunkscan_kernel(const float* __restrict__ init_rot)
{
    __shared__ __align__(16) float4 s_wq[8];
    __shared__ bool s_last;
    int c = blockIdx.x, j = threadIdx.x;
    int lane = j & 31, wid = j >> 5;
    int e = c*256 + j;

    float4 v = g_dq[e];
    #pragma unroll
    for (int off = 1; off < 32; off <<= 1) {
        float4 u = shfl_up_q(v, off);
        if (lane >= off) v = qmul(u, v);
    }
    if (lane == 31) s_wq[wid] = v;
    __syncthreads();
    float4 wp = make_float4(1.f, 0.f, 0.f, 0.f);
    for (int wI = 0; wI < wid; wI++) wp = qmul(wp, s_wq[wI]);
    float4 incl = qmul(wp, v);
    g_pq[e] = incl;
    if (j == 255) g_cq[c] = incl;

    __threadfence();
    __syncthreads();
    if (j == 0) s_last = (atomicAdd(&g_ctr1, 1u) == gridDim.x - 1);
    __syncthreads();
    if (s_last) {
        __threadfence();
        int b = wid;                 // 8 warps == 8 batches
        float4 d0 = g_cq[b*NCHB + 2*lane];
        float4 d1 = g_cq[b*NCHB + 2*lane + 1];
        float4 pr = qmul(d0, d1);
        #pragma unroll
        for (int off = 1; off < 32; off <<= 1) {
            float4 u = shfl_up_q(pr, off);
            if (lane >= off) pr = qmul(u, pr);
        }
        float4 ex = shfl_up_q(pr, 1);
        float4 q0 = make_float4(init_rot[b*4+0], init_rot[b*4+1],
                                init_rot[b*4+2], init_rot[b*4+3]);
        float4 pre0 = (lane == 0) ? q0 : qmul(q0, ex);
        float4 pre1 = qmul(pre0, d0);
        g_cpre[b*NCHB + 2*lane]     = pre0;
        g_cpre[b*NCHB + 2*lane + 1] = pre1;
        __syncthreads();
        if (j == 0) g_ctr1 = 0;
    }
}

// ---------------------------------------------------------------------------
// K2: world accel + rot out + within-chunk TSC scan + last-block chunk scan
// grid = 512, block = 256
// ---------------------------------------------------------------------------
__global__ void __launch_bounds__(256)
accel_kernel(const float* __restrict__ dt,
             const float* __restrict__ init_pos, const float* __restrict__ init_vel,
             float* __restrict__ out)
{
    __shared__ TSC s_wt[8];
    __shared__ bool s_last;
    int c = blockIdx.x, j = threadIdx.x;
    int lane = j & 31, wid = j >> 5;
    int e = c*256 + j;

    float4 cpre = g_cpre[c];
    float4 myq = g_pq[e];
    float4 Ee = (j == 0) ? cpre : qmul(cpre, g_pq[e-1]);
    float rn = rsqrtf(Ee.x*Ee.x + Ee.y*Ee.y + Ee.z*Ee.z + Ee.w*Ee.w);
    float qw = Ee.x*rn, q1 = Ee.y*rn, q2 = Ee.z*rn, q3 = Ee.w*rn;

    float v1 = g_cacc[e*3+0], v2 = g_cacc[e*3+1], v3 = g_cacc[e*3+2];
    float t1 = (q2*v3 - q3*v2) + qw*v1;
    float t2 = (q3*v1 - q1*v3) + qw*v2;
    float t3 = (q1*v2 - q2*v1) + qw*v3;
    float a0 = v1 + 2.0f*(q2*t3 - q3*t2);
    float a1 = v2 + 2.0f*(q3*t1 - q1*t3);
    float a2 = v3 + 2.0f*(q1*t2 - q2*t1) - 9.81007f;

    float4 Ei = qmul(cpre, myq);
    float rn2 = rsqrtf(Ei.x*Ei.x + Ei.y*Ei.y + Ei.z*Ei.z + Ei.w*Ei.w);
    size_t ob = (size_t)e * 16;
    out[ob+6] = Ei.x*rn2; out[ob+7] = Ei.y*rn2;
    out[ob+8] = Ei.z*rn2; out[ob+9] = Ei.w*rn2;

    float dtv = dt[e];
    float hd = 0.5f*dtv*dtv;
    TSC v; v.T = dtv;
    v.S0 = a0*dtv; v.S1 = a1*dtv; v.S2 = a2*dtv;
    v.C0 = a0*hd;  v.C1 = a1*hd;  v.C2 = a2*hd;

    #pragma unroll
    for (int off = 1; off < 32; off <<= 1) {
        TSC u = shfl_up_tsc(v, off);
        if (lane >= off) v = tsc_comb(u, v);
    }
    if (lane == 31) s_wt[wid] = v;
    __syncthreads();
    TSC wp; wp.T=0.f; wp.S0=0.f; wp.S1=0.f; wp.S2=0.f; wp.C0=0.f; wp.C1=0.f; wp.C2=0.f;
    for (int wI = 0; wI < wid; wI++) wp = tsc_comb(wp, s_wt[wI]);
    TSC incl = tsc_comb(wp, v);

    g_eTSC[0*(size_t)NROWS + e] = incl.T;
    g_eTSC[1*(size_t)NROWS + e] = incl.S0;
    g_eTSC[2*(size_t)NROWS + e] = incl.S1;
    g_eTSC[3*(size_t)NROWS + e] = incl.S2;
    g_eTSC[4*(size_t)NROWS + e] = incl.C0;
    g_eTSC[5*(size_t)NROWS + e] = incl.C1;
    g_eTSC[6*(size_t)NROWS + e] = incl.C2;
    if (j == 255) {
        g_cTSC[c*7+0]=incl.T;
        g_cTSC[c*7+1]=incl.S0; g_cTSC[c*7+2]=incl.S1; g_cTSC[c*7+3]=incl.S2;
        g_cTSC[c*7+4]=incl.C0; g_cTSC[c*7+5]=incl.C1; g_cTSC[c*7+6]=incl.C2;
    }

    __threadfence();
    __syncthreads();
    if (j == 0) s_last = (atomicAdd(&g_ctr2, 1u) == gridDim.x - 1);
    __syncthreads();
    if (s_last) {
        __threadfence();
        int b = wid;
        int c0i = b*NCHB + 2*lane, c1i = c0i + 1;
        TSC d0, d1;
        d0.T=g_cTSC[c0i*7+0]; d0.S0=g_cTSC[c0i*7+1]; d0.S1=g_cTSC[c0i*7+2]; d0.S2=g_cTSC[c0i*7+3];
        d0.C0=g_cTSC[c0i*7+4]; d0.C1=g_cTSC[c0i*7+5]; d0.C2=g_cTSC[c0i*7+6];
        d1.T=g_cTSC[c1i*7+0]; d1.S0=g_cTSC[c1i*7+1]; d1.S1=g_cTSC[c1i*7+2]; d1.S2=g_cTSC[c1i*7+3];
        d1.C0=g_cTSC[c1i*7+4]; d1.C1=g_cTSC[c1i*7+5]; d1.C2=g_cTSC[c1i*7+6];
        TSC pr = tsc_comb(d0, d1);
        #pragma unroll
        for (int off = 1; off < 32; off <<= 1) {
            TSC u = shfl_up_tsc(pr, off);
            if (lane >= off) pr = tsc_comb(u, pr);
        }
        TSC ex = shfl_up_tsc(pr, 1);
        if (lane == 0) { ex.T=0.f; ex.S0=0.f; ex.S1=0.f; ex.S2=0.f; ex.C0=0.f; ex.C1=0.f; ex.C2=0.f; }
        TSC ex1 = tsc_comb(ex, d0);
        float ip0 = init_pos[b*3+0], ip1 = init_pos[b*3+1], ip2 = init_pos[b*3+2];
        float iv0 = init_vel[b*3+0], iv1 = init_vel[b*3+1], iv2 = init_vel[b*3+2];
        g_cstart[c0i*6+0] = ip0 + iv0*ex.T + ex.C0;
        g_cstart[c0i*6+1] = ip1 + iv1*ex.T + ex.C1;
        g_cstart[c0i*6+2] = ip2 + iv2*ex.T + ex.C2;
        g_cstart[c0i*6+3] = iv0 + ex.S0;
        g_cstart[c0i*6+4] = iv1 + ex.S1;
        g_cstart[c0i*6+5] = iv2 + ex.S2;
        g_cstart[c1i*6+0] = ip0 + iv0*ex1.T + ex1.C0;
        g_cstart[c1i*6+1] = ip1 + iv1*ex1.T + ex1.C1;
        g_cstart[c1i*6+2] = ip2 + iv2*ex1.T + ex1.C2;
        g_cstart[c1i*6+3] = iv0 + ex1.S0;
        g_cstart[c1i*6+4] = iv1 + ex1.S1;
        g_cstart[c1i*6+5] = iv2 + ex1.S2;
        __syncthreads();
        if (j == 0) g_ctr2 = 0;
    }
}

// ---------------------------------------------------------------------------
// K3: final per-element pos/vel
// ---------------------------------------------------------------------------
__global__ void __launch_bounds__(256)
posvel_kernel(float* __restrict__ out)
{
    int c = blockIdx.x, j = threadIdx.x;
    int e = c*256 + j;
    float ps0 = g_cstart[c*6+0], ps1 = g_cstart[c*6+1], ps2 = g_cstart[c*6+2];
    float vs0 = g_cstart[c*6+3], vs1 = g_cstart[c*6+4], vs2 = g_cstart[c*6+5];
    float T  = g_eTSC[0*(size_t)NROWS + e];
    float S0 = g_eTSC[1*(size_t)NROWS + e];
    float S1 = g_eTSC[2*(size_t)NROWS + e];
    float S2 = g_eTSC[3*(size_t)NROWS + e];
    float C0 = g_eTSC[4*(size_t)NROWS + e];
    float C1 = g_eTSC[5*(size_t)NROWS + e];
    float C2 = g_eTSC[6*(size_t)NROWS + e];
    size_t ob = (size_t)e * 16;
    out[ob+0] = ps0 + vs0*T + C0;
    out[ob+1] = ps1 + vs1*T + C1;
    out[ob+2] = ps2 + vs2*T + C2;
    out[ob+3] = vs0 + S0;
    out[ob+4] = vs1 + S1;
    out[ob+5] = vs2 + S2;
}

// ---------------------------------------------------------------------------
extern "C" void kernel_launch(void* const* d_in, const int* in_sizes, int n_in,
                              void* d_out, int out_size)
{
    const float* acc      = (const float*)d_in[0];
    const float* gyro     = (const float*)d_in[1];
    const float* dt       = (const float*)d_in[2];
    const float* init_pos = (const float*)d_in[3];
    const float* init_vel = (const float*)d_in[4];
    const float* init_rot = (const float*)d_in[5];
    const float* W_enc    = (const float*)d_in[6];
    const float* b_enc    = (const float*)d_in[7];
    const float* W_dec    = (const float*)d_in[8];
    const float* b_dec    = (const float*)d_in[9];
    float* out = (float*)d_out;

    mlp_kernel<<<NROWS/128, 64>>>(acc, gyro, dt, W_enc, b_enc, W_dec, b_dec, out);
    chunkscan_kernel<<<NCHT, 256>>>(init_rot);
    accel_kernel<<<NCHT, 256>>>(dt, init_pos, init_vel, out);
    posvel_kernel<<<NCHT, 256>>>(out);
}

// round 8
// speedup vs baseline: 1.0793x; 1.0793x over previous
#include <cuda_runtime.h>
#include <cuda_bf16.h>

#define BB 8
#define FF 16384
#define HH 256
#define NROWS (BB*FF)
#define CHUNK 256
#define NCHB  (FF/CHUNK)        // 64 chunks per batch
#define NCHT  (BB*NCHB)         // 512 chunks total
#define FGRID (NCHT/2)          // 256 blocks in fused kernel

typedef unsigned long long u64;

// ---------------- scratch (__device__ globals; no allocation) ----------------
__device__ float4 g_dq[NROWS];        // per-row delta quaternion
__device__ float4 g_cq[NCHT];         // per-chunk quat product
__device__ float  g_cacc[NROWS*3];    // corrected acc
__device__ float  g_cTSC[NCHT*7];     // per-chunk TSC summary
__device__ unsigned int g_bar1 = 0;   // monotonic grid-barrier counters
__device__ unsigned int g_bar2 = 0;

// ---------------- packed f32x2 helpers ----------------
__device__ __forceinline__ u64 pk2(float lo, float hi) {
    u64 r; asm("mov.b64 %0,{%1,%2};" : "=l"(r) : "f"(lo), "f"(hi)); return r;
}
__device__ __forceinline__ void upk2(u64 v, float& lo, float& hi) {
    asm("mov.b64 {%0,%1},%2;" : "=f"(lo), "=f"(hi) : "l"(v));
}
__device__ __forceinline__ u64 ffma2(u64 a, u64 b, u64 c) {
    u64 r; asm("fma.rn.f32x2 %0,%1,%2,%3;" : "=l"(r) : "l"(a), "l"(b), "l"(c)); return r;
}
__device__ __forceinline__ u64 fmul2(u64 a, u64 b) {
    u64 r; asm("mul.rn.f32x2 %0,%1,%2;" : "=l"(r) : "l"(a), "l"(b)); return r;
}
__device__ __forceinline__ float tanha(float x) {
    float r; asm("tanh.approx.f32 %0,%1;" : "=f"(r) : "f"(x)); return r;
}

// quaternion as float4: .x=w, .y..w = vector
__device__ __forceinline__ float4 qmul(float4 q, float4 p) {
    float4 r;
    r.x = q.x*p.x - q.y*p.y - q.z*p.z - q.w*p.w;
    r.y = q.x*p.y + p.x*q.y + (q.z*p.w - q.w*p.z);
    r.z = q.x*p.z + p.x*q.z + (q.w*p.y - q.y*p.w);
    r.w = q.x*p.w + p.x*q.w + (q.y*p.z - q.z*p.y);
    return r;
}
__device__ __forceinline__ float4 shfl_up_q(float4 v, int off) {
    float4 r;
    r.x = __shfl_up_sync(0xffffffffu, v.x, off);
    r.y = __shfl_up_sync(0xffffffffu, v.y, off);
    r.z = __shfl_up_sync(0xffffffffu, v.z, off);
    r.w = __shfl_up_sync(0xffffffffu, v.w, off);
    return r;
}

struct TSC { float T, S0, S1, S2, C0, C1, C2; };
__device__ __forceinline__ TSC tsc_comb(const TSC& l, const TSC& r) {
    TSC o;
    o.C0 = l.C0 + r.C0 + l.S0*r.T;
    o.C1 = l.C1 + r.C1 + l.S1*r.T;
    o.C2 = l.C2 + r.C2 + l.S2*r.T;
    o.S0 = l.S0 + r.S0; o.S1 = l.S1 + r.S1; o.S2 = l.S2 + r.S2;
    o.T  = l.T + r.T;
    return o;
}
__device__ __forceinline__ TSC shfl_up_tsc(const TSC& v, int off) {
    TSC r;
    r.T  = __shfl_up_sync(0xffffffffu, v.T, off);
    r.S0 = __shfl_up_sync(0xffffffffu, v.S0, off);
    r.S1 = __shfl_up_sync(0xffffffffu, v.S1, off);
    r.S2 = __shfl_up_sync(0xffffffffu, v.S2, off);
    r.C0 = __shfl_up_sync(0xffffffffu, v.C0, off);
    r.C1 = __shfl_up_sync(0xffffffffu, v.C1, off);
    r.C2 = __shfl_up_sync(0xffffffffu, v.C2, off);
    return r;
}

// monotonic grid barrier: no reset needed -> safe across graph replays
__device__ __forceinline__ void gbar(unsigned int* bar, unsigned int n) {
    __syncthreads();
    if (threadIdx.x == 0) {
        __threadfence();
        unsigned int my = atomicAdd(bar, 1u) + 1u;
        unsigned int target = ((my + n - 1u) / n) * n;
        while ((int)(*(volatile unsigned int*)bar - target) < 0) __nanosleep(64);
    }
    __syncthreads();
}

// per-row tail: corrections -> out, cacc, delta quat -> g_dq
__device__ __forceinline__ void row_tail(
    int r, float c0, float c1, float c2, float c3, float c4, float c5,
    float x0, float x1, float x2, float x3, float x4, float x5,
    const float* __restrict__ dt, float* __restrict__ out)
{
    size_t ob = (size_t)r * 16;
    out[ob+10] = c0; out[ob+11] = c1; out[ob+12] = c2;
    out[ob+13] = c3; out[ob+14] = c4; out[ob+15] = c5;
    g_cacc[r*3+0] = c0 + x0;
    g_cacc[r*3+1] = c1 + x1;
    g_cacc[r*3+2] = c2 + x2;
    float dtv = dt[r];
    float v0 = (c3 + x3) * dtv;
    float v1 = (c4 + x4) * dtv;
    float v2 = (c5 + x5) * dtv;
    float tt2 = v0*v0 + v1*v1 + v2*v2;
    float theta = sqrtf(tt2 + 1e-16f);
    float half  = 0.5f * theta;
    float w  = cosf(half);
    float sc = (tt2 < 1e-12f) ? (0.5f - tt2 * (1.0f/48.0f)) : (sinf(half) / theta);
    g_dq[r] = make_float4(w, v0*sc, v1*sc, v2*sc);
}

// ---------------------------------------------------------------------------
// K1: MLP only (at FFMA2 pipe floor). grid = 1024 x 64, 2 rows/thread,
//     whole grid resident in one wave -> balanced across SMs.
// ---------------------------------------------------------------------------
__global__ void __launch_bounds__(64)
mlp_kernel(const float* __restrict__ acc, const float* __restrict__ gyro,
           const float* __restrict__ dt,
           const float* __restrict__ W_enc, const float* __restrict__ b_enc,
           const float* __restrict__ W_dec, const float* __restrict__ b_dec,
           float* __restrict__ out)
{
    __shared__ __align__(16) u64 s_w[128*16];
    int tid = threadIdx.x;

    #pragma unroll
    for (int pp = 0; pp < 2; pp++) {
        int p = tid + pp*64;
        #pragma unroll
        for (int k = 0; k < 6; k++) {
            const float2 v = reinterpret_cast<const float2*>(W_enc + k*HH)[p];
            s_w[p*16 + k] = pk2(v.x, v.y);
        }
        const float2 bb = reinterpret_cast<const float2*>(b_enc)[p];
        s_w[p*16 + 6] = pk2(bb.x, bb.y);
        #pragma unroll
        for (int k = 0; k < 6; k++) {
            s_w[p*16 + 7 + k] = pk2(W_dec[(2*p)*6 + k], W_dec[(2*p+1)*6 + k]);
        }
        s_w[p*16 + 13] = 0; s_w[p*16 + 14] = 0; s_w[p*16 + 15] = 0;
    }
    __syncthreads();

    int rA = blockIdx.x * 128 + tid;
    int rB = rA + 64;
    float xA0 = acc[rA*3+0], xA1 = acc[rA*3+1], xA2 = acc[rA*3+2];
    float xA3 = gyro[rA*3+0], xA4 = gyro[rA*3+1], xA5 = gyro[rA*3+2];
    float xB0 = acc[rB*3+0], xB1 = acc[rB*3+1], xB2 = acc[rB*3+2];
    float xB3 = gyro[rB*3+0], xB4 = gyro[rB*3+1], xB5 = gyro[rB*3+2];
    u64 XA0 = pk2(xA0,xA0), XA1 = pk2(xA1,xA1), XA2 = pk2(xA2,xA2);
    u64 XA3 = pk2(xA3,xA3), XA4 = pk2(xA4,xA4), XA5 = pk2(xA5,xA5);
    u64 XB0 = pk2(xB0,xB0), XB1 = pk2(xB1,xB1), XB2 = pk2(xB2,xB2);
    u64 XB3 = pk2(xB3,xB3), XB4 = pk2(xB4,xB4), XB5 = pk2(xB5,xB5);

    u64 CU1 = pk2(0.7978845608028654f, 0.7978845608028654f);
    u64 CU3 = pk2(0.035677408136300125f, 0.035677408136300125f);
    u64 HLF = pk2(0.5f, 0.5f);

    u64 aA0=0,aA1=0,aA2=0,aA3=0,aA4=0,aA5=0;
    u64 aB0=0,aB1=0,aB2=0,aB3=0,aB4=0,aB5=0;

    #pragma unroll 2
    for (int p = 0; p < 128; p++) {
        const ulonglong2* q = reinterpret_cast<const ulonglong2*>(s_w + p*16);
        ulonglong2 q0 = q[0], q1 = q[1], q2 = q[2], q3 = q[3], q4 = q[4], q5 = q[5];
        u64 dec5 = reinterpret_cast<const u64*>(s_w + p*16)[12];

        u64 preA = q3.x, preB = q3.x;
        preA = ffma2(q0.x, XA0, preA);  preB = ffma2(q0.x, XB0, preB);
        preA = ffma2(q0.y, XA1, preA);  preB = ffma2(q0.y, XB1, preB);
        preA = ffma2(q1.x, XA2, preA);  preB = ffma2(q1.x, XB2, preB);
        preA = ffma2(q1.y, XA3, preA);  preB = ffma2(q1.y, XB3, preB);
        preA = ffma2(q2.x, XA4, preA);  preB = ffma2(q2.x, XB4, preB);
        preA = ffma2(q2.y, XA5, preA);  preB = ffma2(q2.y, XB5, preB);

        u64 s2A = fmul2(preA, preA);    u64 s2B = fmul2(preB, preB);
        u64 t2A = ffma2(s2A, CU3, CU1); u64 t2B = ffma2(s2B, CU3, CU1);
        u64 upA = fmul2(preA, t2A);     u64 upB = fmul2(preB, t2B);
        float uA0, uA1, uB0, uB1;
        upk2(upA, uA0, uA1); upk2(upB, uB0, uB1);
        u64 thA = pk2(tanha(uA0), tanha(uA1));
        u64 thB = pk2(tanha(uB0), tanha(uB1));
        u64 omA = ffma2(thA, HLF, HLF); u64 omB = ffma2(thB, HLF, HLF);
        u64 ftA = fmul2(preA, omA);     u64 ftB = fmul2(preB, omB);

        aA0 = ffma2(ftA, q3.y, aA0);    aB0 = ffma2(ftB, q3.y, aB0);
        aA1 = ffma2(ftA, q4.x, aA1);    aB1 = ffma2(ftB, q4.x, aB1);
        aA2 = ffma2(ftA, q4.y, aA2);    aB2 = ffma2(ftB, q4.y, aB2);
        aA3 = ffma2(ftA, q5.x, aA3);    aB3 = ffma2(ftB, q5.x, aB3);
        aA4 = ffma2(ftA, q5.y, aA4);    aB4 = ffma2(ftB, q5.y, aB4);
        aA5 = ffma2(ftA, dec5, aA5);    aB5 = ffma2(ftB, dec5, aB5);
    }

    float bd0 = __ldg(&b_dec[0]), bd1 = __ldg(&b_dec[1]), bd2 = __ldg(&b_dec[2]);
    float bd3 = __ldg(&b_dec[3]), bd4 = __ldg(&b_dec[4]), bd5 = __ldg(&b_dec[5]);
    float lo, hi;
    float cA0, cA1, cA2, cA3, cA4, cA5, cB0, cB1, cB2, cB3, cB4, cB5;
    upk2(aA0, lo, hi); cA0 = lo + hi + bd0;
    upk2(aA1, lo, hi); cA1 = lo + hi + bd1;
    upk2(aA2, lo, hi); cA2 = lo + hi + bd2;
    upk2(aA3, lo, hi); cA3 = lo + hi + bd3;
    upk2(aA4, lo, hi); cA4 = lo + hi + bd4;
    upk2(aA5, lo, hi); cA5 = lo + hi + bd5;
    upk2(aB0, lo, hi); cB0 = lo + hi + bd0;
    upk2(aB1, lo, hi); cB1 = lo + hi + bd1;
    upk2(aB2, lo, hi); cB2 = lo + hi + bd2;
    upk2(aB3, lo, hi); cB3 = lo + hi + bd3;
    upk2(aB4, lo, hi); cB4 = lo + hi + bd4;
    upk2(aB5, lo, hi); cB5 = lo + hi + bd5;

    row_tail(rA, cA0,cA1,cA2,cA3,cA4,cA5, xA0,xA1,xA2,xA3,xA4,xA5, dt, out);
    row_tail(rB, cB0,cB1,cB2,cB3,cB4,cB5, xB0,xB1,xB2,xB3,xB4,xB5, dt, out);
}

// ---------------------------------------------------------------------------
// K2 (fused): chunk quat scans -> grid barrier -> cross-chunk quat prefix
//   -> accel + rot + chunk TSC scans -> grid barrier -> cross-chunk TSC
//   -> final pos/vel.  TSC stays in registers across barrier 2.
// grid = 256 blocks x 256 threads; 2 blocks/SM forced -> all co-resident.
// ---------------------------------------------------------------------------
__global__ void __launch_bounds__(256, 2)
fused_kernel(const float* __restrict__ dt,
             const float* __restrict__ init_pos, const float* __restrict__ init_vel,
             const float* __restrict__ init_rot, float* __restrict__ out)
{
    __shared__ __align__(16) float4 s_q[2][256];
    __shared__ __align__(16) float4 s_wq[8];
    __shared__ __align__(16) float4 s_cpre[2];
    __shared__ TSC s_wt[8];
    __shared__ float s_start[12];
    int j = threadIdx.x, lane = j & 31, wid = j >> 5;
    int c0 = blockIdx.x * 2;
    int b  = c0 / NCHB;
    int pairlane = (c0 % NCHB) >> 1;   // lane in warp0 that owns this block's chunk pair

    // ---- Phase A: within-chunk quat scans for both chunks ----
    #pragma unroll
    for (int s = 0; s < 2; s++) {
        float4 v = g_dq[(c0+s)*256 + j];
        #pragma unroll
        for (int off = 1; off < 32; off <<= 1) {
            float4 u = shfl_up_q(v, off);
            if (lane >= off) v = qmul(u, v);
        }
        if (lane == 31) s_wq[wid] = v;
        __syncthreads();
        float4 wp = make_float4(1.f, 0.f, 0.f, 0.f);
        for (int wI = 0; wI < wid; wI++) wp = qmul(wp, s_wq[wI]);
        float4 incl = qmul(wp, v);
        s_q[s][j] = incl;
        if (j == 255) g_cq[c0+s] = incl;
        __syncthreads();
    }

    // ---- grid barrier 1 ----
    gbar(&g_bar1, FGRID);

    // ---- cross-chunk quat prefix (warp 0, redundant per block) ----
    if (wid == 0) {
        float4 d0 = __ldcg(&g_cq[b*NCHB + 2*lane]);
        float4 d1 = __ldcg(&g_cq[b*NCHB + 2*lane + 1]);
        float4 pr = qmul(d0, d1);
        #pragma unroll
        for (int off = 1; off < 32; off <<= 1) {
            float4 u = shfl_up_q(pr, off);
            if (lane >= off) pr = qmul(u, pr);
        }
        float4 ex = shfl_up_q(pr, 1);
        float4 q0 = make_float4(init_rot[b*4+0], init_rot[b*4+1],
                                init_rot[b*4+2], init_rot[b*4+3]);
        float4 pre0 = (lane == 0) ? q0 : qmul(q0, ex);
        float4 pre1 = qmul(pre0, d0);
        if (lane == pairlane) { s_cpre[0] = pre0; s_cpre[1] = pre1; }
    }
    __syncthreads();

    // ---- Phase B: accel, rot out, within-chunk TSC scans ----
    TSC inclT[2];
    #pragma unroll
    for (int s = 0; s < 2; s++) {
        int e = (c0+s)*256 + j;
        float4 cpre = s_cpre[s];
        float4 myq  = s_q[s][j];
        float4 Ee = (j == 0) ? cpre : qmul(cpre, s_q[s][j-1]);
        float rn = rsqrtf(Ee.x*Ee.x + Ee.y*Ee.y + Ee.z*Ee.z + Ee.w*Ee.w);
        float qw = Ee.x*rn, q1 = Ee.y*rn, q2 = Ee.z*rn, q3 = Ee.w*rn;

        float v1 = g_cacc[e*3+0], v2 = g_cacc[e*3+1], v3 = g_cacc[e*3+2];
        float t1 = (q2*v3 - q3*v2) + qw*v1;
        float t2 = (q3*v1 - q1*v3) + qw*v2;
        float t3 = (q1*v2 - q2*v1) + qw*v3;
        float a0 = v1 + 2.0f*(q2*t3 - q3*t2);
        float a1 = v2 + 2.0f*(q3*t1 - q1*t3);
        float a2 = v3 + 2.0f*(q1*t2 - q2*t1) - 9.81007f;

        float4 Ei = qmul(cpre, myq);
        float rn2 = rsqrtf(Ei.x*Ei.x + Ei.y*Ei.y + Ei.z*Ei.z + Ei.w*Ei.w);
        size_t ob = (size_t)e * 16;
        out[ob+6] = Ei.x*rn2; out[ob+7] = Ei.y*rn2;
        out[ob+8] = Ei.z*rn2; out[ob+9] = Ei.w*rn2;

        float dtv = dt[e];
        float hd = 0.5f*dtv*dtv;
        TSC v; v.T = dtv;
        v.S0 = a0*dtv; v.S1 = a1*dtv; v.S2 = a2*dtv;
        v.C0 = a0*hd;  v.C1 = a1*hd;  v.C2 = a2*hd;

        #pragma unroll
        for (int off = 1; off < 32; off <<= 1) {
            TSC u = shfl_up_tsc(v, off);
            if (lane >= off) v = tsc_comb(u, v);
        }
        if (lane == 31) s_wt[wid] = v;
        __syncthreads();
        TSC wp; wp.T=0.f; wp.S0=0.f; wp.S1=0.f; wp.S2=0.f; wp.C0=0.f; wp.C1=0.f; wp.C2=0.f;
        for (int wI = 0; wI < wid; wI++) wp = tsc_comb(wp, s_wt[wI]);
        inclT[s] = tsc_comb(wp, v);
        if (j == 255) {
            int c = c0 + s;
            g_cTSC[c*7+0]=inclT[s].T;
            g_cTSC[c*7+1]=inclT[s].S0; g_cTSC[c*7+2]=inclT[s].S1; g_cTSC[c*7+3]=inclT[s].S2;
            g_cTSC[c*7+4]=inclT[s].C0; g_cTSC[c*7+5]=inclT[s].C1; g_cTSC[c*7+6]=inclT[s].C2;
        }
        __syncthreads();
    }

    // ---- grid barrier 2 ----
    gbar(&g_bar2, FGRID);

    // ---- cross-chunk TSC prefix -> per-chunk start states (warp 0) ----
    if (wid == 0) {
        int c0i = b*NCHB + 2*lane, c1i = c0i + 1;
        TSC d0, d1;
        d0.T =__ldcg(&g_cTSC[c0i*7+0]);
        d0.S0=__ldcg(&g_cTSC[c0i*7+1]); d0.S1=__ldcg(&g_cTSC[c0i*7+2]); d0.S2=__ldcg(&g_cTSC[c0i*7+3]);
        d0.C0=__ldcg(&g_cTSC[c0i*7+4]); d0.C1=__ldcg(&g_cTSC[c0i*7+5]); d0.C2=__ldcg(&g_cTSC[c0i*7+6]);
        d1.T =__ldcg(&g_cTSC[c1i*7+0]);
        d1.S0=__ldcg(&g_cTSC[c1i*7+1]); d1.S1=__ldcg(&g_cTSC[c1i*7+2]); d1.S2=__ldcg(&g_cTSC[c1i*7+3]);
        d1.C0=__ldcg(&g_cTSC[c1i*7+4]); d1.C1=__ldcg(&g_cTSC[c1i*7+5]); d1.C2=__ldcg(&g_cTSC[c1i*7+6]);
        TSC pr = tsc_comb(d0, d1);
        #pragma unroll
        for (int off = 1; off < 32; off <<= 1) {
            TSC u = shfl_up_tsc(pr, off);
            if (lane >= off) pr = tsc_comb(u, pr);
        }
        TSC ex = shfl_up_tsc(pr, 1);
        if (lane == 0) { ex.T=0.f; ex.S0=0.f; ex.S1=0.f; ex.S2=0.f; ex.C0=0.f; ex.C1=0.f; ex.C2=0.f; }
        TSC ex1 = tsc_comb(ex, d0);
        if (lane == pairlane) {
            float ip0 = init_pos[b*3+0], ip1 = init_pos[b*3+1], ip2 = init_pos[b*3+2];
            float iv0 = init_vel[b*3+0], iv1 = init_vel[b*3+1], iv2 = init_vel[b*3+2];
            s_start[0] = ip0 + iv0*ex.T + ex.C0;
            s_start[1] = ip1 + iv1*ex.T + ex.C1;
            s_start[2] = ip2 + iv2*ex.T + ex.C2;
            s_start[3] = iv0 + ex.S0;
            s_start[4] = iv1 + ex.S1;
            s_start[5] = iv2 + ex.S2;
            s_start[6] = ip0 + iv0*ex1.T + ex1.C0;
            s_start[7] = ip1 + iv1*ex1.T + ex1.C1;
            s_start[8] = ip2 + iv2*ex1.T + ex1.C2;
            s_start[9]  = iv0 + ex1.S0;
            s_start[10] = iv1 + ex1.S1;
            s_start[11] = iv2 + ex1.S2;
        }
    }
    __syncthreads();

    // ---- Phase C: final pos/vel from in-register TSC ----
    #pragma unroll
    for (int s = 0; s < 2; s++) {
        int e = (c0+s)*256 + j;
        TSC t = inclT[s];
        float ps0 = s_start[s*6+0], ps1 = s_start[s*6+1], ps2 = s_start[s*6+2];
        float vs0 = s_start[s*6+3], vs1 = s_start[s*6+4], vs2 = s_start[s*6+5];
        size_t ob = (size_t)e * 16;
        out[ob+0] = ps0 + vs0*t.T + t.C0;
        out[ob+1] = ps1 + vs1*t.T + t.C1;
        out[ob+2] = ps2 + vs2*t.T + t.C2;
        out[ob+3] = vs0 + t.S0;
        out[ob+4] = vs1 + t.S1;
        out[ob+5] = vs2 + t.S2;
    }
}

// ---------------------------------------------------------------------------
extern "C" void kernel_launch(void* const* d_in, const int* in_sizes, int n_in,
                              void* d_out, int out_size)
{
    const float* acc      = (const float*)d_in[0];
    const float* gyro     = (const float*)d_in[1];
    const float* dt       = (const float*)d_in[2];
    const float* init_pos = (const float*)d_in[3];
    const float* init_vel = (const float*)d_in[4];
    const float* init_rot = (const float*)d_in[5];
    const float* W_enc    = (const float*)d_in[6];
    const float* b_enc    = (const float*)d_in[7];
    const float* W_dec    = (const float*)d_in[8];
    const float* b_dec    = (const float*)d_in[9];
    float* out = (float*)d_out;

    mlp_kernel<<<NROWS/128, 64>>>(acc, gyro, dt, W_enc, b_enc, W_dec, b_dec, out);
    fused_kernel<<<FGRID, 256>>>(dt, init_pos, init_vel, init_rot, out);
}

// round 10
// speedup vs baseline: 1.1238x; 1.0413x over previous
#include <cuda_runtime.h>
#include <cuda_bf16.h>

#define BB 8
#define FF 16384
#define HH 256
#define NROWS (BB*FF)
#define CHUNK 256
#define NCHB  (FF/CHUNK)        // 64 chunks per batch
#define NCHT  (BB*NCHB)         // 512 chunks total

typedef unsigned long long u64;

// ---------------- scratch (__device__ globals; no allocation) ----------------
__device__ float4 g_dq[NROWS];        // per-row delta quaternion
__device__ float4 g_cq[NCHT];         // per-chunk quat product
__device__ float4 g_cacc4[NROWS];     // corrected acc (xyz, pad)
__device__ float  g_cTSC[NCHT*7];     // per-chunk TSC summary
__device__ unsigned int g_bar1 = 0;   // monotonic grid-barrier counters
__device__ unsigned int g_bar2 = 0;

// ---------------- packed f32x2 helpers ----------------
__device__ __forceinline__ u64 pk2(float lo, float hi) {
    u64 r; asm("mov.b64 %0,{%1,%2};" : "=l"(r) : "f"(lo), "f"(hi)); return r;
}
__device__ __forceinline__ void upk2(u64 v, float& lo, float& hi) {
    asm("mov.b64 {%0,%1},%2;" : "=f"(lo), "=f"(hi) : "l"(v));
}
__device__ __forceinline__ u64 ffma2(u64 a, u64 b, u64 c) {
    u64 r; asm("fma.rn.f32x2 %0,%1,%2,%3;" : "=l"(r) : "l"(a), "l"(b), "l"(c)); return r;
}
__device__ __forceinline__ u64 fmul2(u64 a, u64 b) {
    u64 r; asm("mul.rn.f32x2 %0,%1,%2;" : "=l"(r) : "l"(a), "l"(b)); return r;
}
__device__ __forceinline__ float tanha(float x) {
    float r; asm("tanh.approx.f32 %0,%1;" : "=f"(r) : "f"(x)); return r;
}

// quaternion as float4: .x=w, .y..w = vector
__device__ __forceinline__ float4 qmul(float4 q, float4 p) {
    float4 r;
    r.x = q.x*p.x - q.y*p.y - q.z*p.z - q.w*p.w;
    r.y = q.x*p.y + p.x*q.y + (q.z*p.w - q.w*p.z);
    r.z = q.x*p.z + p.x*q.z + (q.w*p.y - q.y*p.w);
    r.w = q.x*p.w + p.x*q.w + (q.y*p.z - q.z*p.y);
    return r;
}
__device__ __forceinline__ float4 shfl_up_q(float4 v, int off) {
    float4 r;
    r.x = __shfl_up_sync(0xffffffffu, v.x, off);
    r.y = __shfl_up_sync(0xffffffffu, v.y, off);
    r.z = __shfl_up_sync(0xffffffffu, v.z, off);
    r.w = __shfl_up_sync(0xffffffffu, v.w, off);
    return r;
}

struct TSC { float T, S0, S1, S2, C0, C1, C2; };
__device__ __forceinline__ TSC tsc_comb(const TSC& l, const TSC& r) {
    TSC o;
    o.C0 = l.C0 + r.C0 + l.S0*r.T;
    o.C1 = l.C1 + r.C1 + l.S1*r.T;
    o.C2 = l.C2 + r.C2 + l.S2*r.T;
    o.S0 = l.S0 + r.S0; o.S1 = l.S1 + r.S1; o.S2 = l.S2 + r.S2;
    o.T  = l.T + r.T;
    return o;
}
__device__ __forceinline__ TSC shfl_up_tsc(const TSC& v, int off) {
    TSC r;
    r.T  = __shfl_up_sync(0xffffffffu, v.T, off);
    r.S0 = __shfl_up_sync(0xffffffffu, v.S0, off);
    r.S1 = __shfl_up_sync(0xffffffffu, v.S1, off);
    r.S2 = __shfl_up_sync(0xffffffffu, v.S2, off);
    r.C0 = __shfl_up_sync(0xffffffffu, v.C0, off);
    r.C1 = __shfl_up_sync(0xffffffffu, v.C1, off);
    r.C2 = __shfl_up_sync(0xffffffffu, v.C2, off);
    return r;
}

// monotonic grid barrier: no reset needed -> safe across graph replays
__device__ __forceinline__ void gbar(unsigned int* bar, unsigned int n) {
    __syncthreads();
    if (threadIdx.x == 0) {
        __threadfence();
        unsigned int my = atomicAdd(bar, 1u) + 1u;
        unsigned int target = ((my + n - 1u) / n) * n;
        while ((int)(*(volatile unsigned int*)bar - target) < 0) __nanosleep(32);
    }
    __syncthreads();
}

// per-row tail: corrections -> out (float2s), cacc -> g_cacc4, delta quat -> g_dq
__device__ __forceinline__ void row_tail(
    int r, float c0, float c1, float c2, float c3, float c4, float c5,
    float x0, float x1, float x2, float x3, float x4, float x5,
    const float* __restrict__ dt, float* __restrict__ out)
{
    size_t ob = (size_t)r * 16;
    float2* o2 = reinterpret_cast<float2*>(out + ob + 10);
    o2[0] = make_float2(c0, c1);
    o2[1] = make_float2(c2, c3);
    o2[2] = make_float2(c4, c5);
    g_cacc4[r] = make_float4(c0 + x0, c1 + x1, c2 + x2, 0.f);
    float dtv = dt[r];
    float v0 = (c3 + x3) * dtv;
    float v1 = (c4 + x4) * dtv;
    float v2 = (c5 + x5) * dtv;
    float tt2 = v0*v0 + v1*v1 + v2*v2;
    float theta = sqrtf(tt2 + 1e-16f);
    float half  = 0.5f * theta;
    float w  = cosf(half);
    float sc = (tt2 < 1e-12f) ? (0.5f - tt2 * (1.0f/48.0f)) : (sinf(half) / theta);
    g_dq[r] = make_float4(w, v0*sc, v1*sc, v2*sc);
}

// ---------------------------------------------------------------------------
// K1: MLP only (at FFMA2 pipe floor). grid = 1024 x 64, 2 rows/thread,
//     whole grid resident in one wave -> balanced across SMs.
// ---------------------------------------------------------------------------
__global__ void __launch_bounds__(64)
mlp_kernel(const float* __restrict__ acc, const float* __restrict__ gyro,
           const float* __restrict__ dt,
           const float* __restrict__ W_enc, const float* __restrict__ b_enc,
           const float* __restrict__ W_dec, const float* __restrict__ b_dec,
           float* __restrict__ out)
{
    __shared__ __align__(16) u64 s_w[128*16];
    int tid = threadIdx.x;

    #pragma unroll
    for (int pp = 0; pp < 2; pp++) {
        int p = tid + pp*64;
        #pragma unroll
        for (int k = 0; k < 6; k++) {
            const float2 v = reinterpret_cast<const float2*>(W_enc + k*HH)[p];
            s_w[p*16 + k] = pk2(v.x, v.y);
        }
        const float2 bb = reinterpret_cast<const float2*>(b_enc)[p];
        s_w[p*16 + 6] = pk2(bb.x, bb.y);
        #pragma unroll
        for (int k = 0; k < 6; k++) {
            s_w[p*16 + 7 + k] = pk2(W_dec[(2*p)*6 + k], W_dec[(2*p+1)*6 + k]);
        }
        s_w[p*16 + 13] = 0; s_w[p*16 + 14] = 0; s_w[p*16 + 15] = 0;
    }
    __syncthreads();

    int rA = blockIdx.x * 128 + tid;
    int rB = rA + 64;
    float xA0 = acc[rA*3+0], xA1 = acc[rA*3+1], xA2 = acc[rA*3+2];
    float xA3 = gyro[rA*3+0], xA4 = gyro[rA*3+1], xA5 = gyro[rA*3+2];
    float xB0 = acc[rB*3+0], xB1 = acc[rB*3+1], xB2 = acc[rB*3+2];
    float xB3 = gyro[rB*3+0], xB4 = gyro[rB*3+1], xB5 = gyro[rB*3+2];
    u64 XA0 = pk2(xA0,xA0), XA1 = pk2(xA1,xA1), XA2 = pk2(xA2,xA2);
    u64 XA3 = pk2(xA3,xA3), XA4 = pk2(xA4,xA4), XA5 = pk2(xA5,xA5);
    u64 XB0 = pk2(xB0,xB0), XB1 = pk2(xB1,xB1), XB2 = pk2(xB2,xB2);
    u64 XB3 = pk2(xB3,xB3), XB4 = pk2(xB4,xB4), XB5 = pk2(xB5,xB5);

    u64 CU1 = pk2(0.7978845608028654f, 0.7978845608028654f);
    u64 CU3 = pk2(0.035677408136300125f, 0.035677408136300125f);
    u64 HLF = pk2(0.5f, 0.5f);

    u64 aA0=0,aA1=0,aA2=0,aA3=0,aA4=0,aA5=0;
    u64 aB0=0,aB1=0,aB2=0,aB3=0,aB4=0,aB5=0;

    #pragma unroll 2
    for (int p = 0; p < 128; p++) {
        const ulonglong2* q = reinterpret_cast<const ulonglong2*>(s_w + p*16);
        ulonglong2 q0 = q[0], q1 = q[1], q2 = q[2], q3 = q[3], q4 = q[4], q5 = q[5];
        u64 dec5 = reinterpret_cast<const u64*>(s_w + p*16)[12];

        u64 preA = q3.x, preB = q3.x;
        preA = ffma2(q0.x, XA0, preA);  preB = ffma2(q0.x, XB0, preB);
        preA = ffma2(q0.y, XA1, preA);  preB = ffma2(q0.y, XB1, preB);
        preA = ffma2(q1.x, XA2, preA);  preB = ffma2(q1.x, XB2, preB);
        preA = ffma2(q1.y, XA3, preA);  preB = ffma2(q1.y, XB3, preB);
        preA = ffma2(q2.x, XA4, preA);  preB = ffma2(q2.x, XB4, preB);
        preA = ffma2(q2.y, XA5, preA);  preB = ffma2(q2.y, XB5, preB);

        u64 s2A = fmul2(preA, preA);    u64 s2B = fmul2(preB, preB);
        u64 t2A = ffma2(s2A, CU3, CU1); u64 t2B = ffma2(s2B, CU3, CU1);
        u64 upA = fmul2(preA, t2A);     u64 upB = fmul2(preB, t2B);
        float uA0, uA1, uB0, uB1;
        upk2(upA, uA0, uA1); upk2(upB, uB0, uB1);
        u64 thA = pk2(tanha(uA0), tanha(uA1));
        u64 thB = pk2(tanha(uB0), tanha(uB1));
        u64 omA = ffma2(thA, HLF, HLF); u64 omB = ffma2(thB, HLF, HLF);
        u64 ftA = fmul2(preA, omA);     u64 ftB = fmul2(preB, omB);

        aA0 = ffma2(ftA, q3.y, aA0);    aB0 = ffma2(ftB, q3.y, aB0);
        aA1 = ffma2(ftA, q4.x, aA1);    aB1 = ffma2(ftB, q4.x, aB1);
        aA2 = ffma2(ftA, q4.y, aA2);    aB2 = ffma2(ftB, q4.y, aB2);
        aA3 = ffma2(ftA, q5.x, aA3);    aB3 = ffma2(ftB, q5.x, aB3);
        aA4 = ffma2(ftA, q5.y, aA4);    aB4 = ffma2(ftB, q5.y, aB4);
        aA5 = ffma2(ftA, dec5, aA5);    aB5 = ffma2(ftB, dec5, aB5);
    }

    float bd0 = __ldg(&b_dec[0]), bd1 = __ldg(&b_dec[1]), bd2 = __ldg(&b_dec[2]);
    float bd3 = __ldg(&b_dec[3]), bd4 = __ldg(&b_dec[4]), bd5 = __ldg(&b_dec[5]);
    float lo, hi;
    float cA0, cA1, cA2, cA3, cA4, cA5, cB0, cB1, cB2, cB3, cB4, cB5;
    upk2(aA0, lo, hi); cA0 = lo + hi + bd0;
    upk2(aA1, lo, hi); cA1 = lo + hi + bd1;
    upk2(aA2, lo, hi); cA2 = lo + hi + bd2;
    upk2(aA3, lo, hi); cA3 = lo + hi + bd3;
    upk2(aA4, lo, hi); cA4 = lo + hi + bd4;
    upk2(aA5, lo, hi); cA5 = lo + hi + bd5;
    upk2(aB0, lo, hi); cB0 = lo + hi + bd0;
    upk2(aB1, lo, hi); cB1 = lo + hi + bd1;
    upk2(aB2, lo, hi); cB2 = lo + hi + bd2;
    upk2(aB3, lo, hi); cB3 = lo + hi + bd3;
    upk2(aB4, lo, hi); cB4 = lo + hi + bd4;
    upk2(aB5, lo, hi); cB5 = lo + hi + bd5;

    row_tail(rA, cA0,cA1,cA2,cA3,cA4,cA5, xA0,xA1,xA2,xA3,xA4,xA5, dt, out);
    row_tail(rB, cB0,cB1,cB2,cB3,cB4,cB5, xB0,xB1,xB2,xB3,xB4,xB5, dt, out);
}

// ---------------------------------------------------------------------------
// K2 (fused): one chunk per block, all 512 blocks co-resident (4/SM).
//   chunk quat scan -> grid barrier -> cross-chunk quat prefix
//   -> accel + rot + chunk TSC scan -> grid barrier -> cross-chunk TSC
//   -> final pos/vel. TSC stays in registers across barrier 2.
// ---------------------------------------------------------------------------
__global__ void __launch_bounds__(256, 4)
fused_kernel(const float* __restrict__ dt,
             const float* __restrict__ init_pos, const float* __restrict__ init_vel,
             const float* __restrict__ init_rot, float* __restrict__ out)
{
    __shared__ __align__(16) float4 s_q[256];
    __shared__ __align__(16) float4 s_wq[8];
    __shared__ __align__(16) float4 s_cpre;
    __shared__ TSC s_wt[8];
    __shared__ float s_start[6];
    int j = threadIdx.x, lane = j & 31, wid = j >> 5;
    int c = blockIdx.x;
    int b  = c / NCHB;
    int cb = c % NCHB;
    int pairlane = cb >> 1;
    int odd = cb & 1;
    int e = c*256 + j;

    // ---- Phase A: within-chunk quat scan ----
    float4 v = g_dq[e];
    #pragma unroll
    for (int off = 1; off < 32; off <<= 1) {
        float4 u = shfl_up_q(v, off);
        if (lane >= off) v = qmul(u, v);
    }
    if (lane == 31) s_wq[wid] = v;
    __syncthreads();
    float4 wp = make_float4(1.f, 0.f, 0.f, 0.f);
    for (int wI = 0; wI < wid; wI++) wp = qmul(wp, s_wq[wI]);
    float4 incl = qmul(wp, v);
    s_q[j] = incl;
    if (j == 255) g_cq[c] = incl;

    // ---- grid barrier 1 ----
    gbar(&g_bar1, NCHT);

    // ---- cross-chunk quat prefix (warp 0, redundant per block) ----
    if (wid == 0) {
        float4 d0 = __ldcg(&g_cq[b*NCHB + 2*lane]);
        float4 d1 = __ldcg(&g_cq[b*NCHB + 2*lane + 1]);
        float4 pr = qmul(d0, d1);
        #pragma unroll
        for (int off = 1; off < 32; off <<= 1) {
            float4 u = shfl_up_q(pr, off);
            if (lane >= off) pr = qmul(u, pr);
        }
        float4 ex = shfl_up_q(pr, 1);
        float4 q0 = make_float4(init_rot[b*4+0], init_rot[b*4+1],
                                init_rot[b*4+2], init_rot[b*4+3]);
        float4 pre0 = (lane == 0) ? q0 : qmul(q0, ex);
        if (lane == pairlane) s_cpre = odd ? qmul(pre0, d0) : pre0;
    }
    __syncthreads();

    // ---- Phase B: accel, rot out, within-chunk TSC scan ----
    float4 cpre = s_cpre;
    float4 myq  = s_q[j];
    float4 Ee = (j == 0) ? cpre : qmul(cpre, s_q[j-1]);
    float rn = rsqrtf(Ee.x*Ee.x + Ee.y*Ee.y + Ee.z*Ee.z + Ee.w*Ee.w);
    float qw = Ee.x*rn, q1 = Ee.y*rn, q2 = Ee.z*rn, q3 = Ee.w*rn;

    float4 ca = g_cacc4[e];
    float v1 = ca.x, v2 = ca.y, v3 = ca.z;
    float t1 = (q2*v3 - q3*v2) + qw*v1;
    float t2 = (q3*v1 - q1*v3) + qw*v2;
    float t3 = (q1*v2 - q2*v1) + qw*v3;
    float a0 = v1 + 2.0f*(q2*t3 - q3*t2);
    float a1 = v2 + 2.0f*(q3*t1 - q1*t3);
    float a2 = v3 + 2.0f*(q1*t2 - q2*t1) - 9.81007f;

    float4 Ei = qmul(cpre, myq);
    float rn2 = rsqrtf(Ei.x*Ei.x + Ei.y*Ei.y + Ei.z*Ei.z + Ei.w*Ei.w);
    size_t ob = (size_t)e * 16;
    {
        float2* r2 = reinterpret_cast<float2*>(out + ob + 6);
        r2[0] = make_float2(Ei.x*rn2, Ei.y*rn2);
        r2[1] = make_float2(Ei.z*rn2, Ei.w*rn2);
    }

    float dtv = dt[e];
    float hd = 0.5f*dtv*dtv;
    TSC tv; tv.T = dtv;
    tv.S0 = a0*dtv; tv.S1 = a1*dtv; tv.S2 = a2*dtv;
    tv.C0 = a0*hd;  tv.C1 = a1*hd;  tv.C2 = a2*hd;

    #pragma unroll
    for (int off = 1; off < 32; off <<= 1) {
        TSC u = shfl_up_tsc(tv, off);
        if (lane >= off) tv = tsc_comb(u, tv);
    }
    if (lane == 31) s_wt[wid] = tv;
    __syncthreads();
    TSC twp; twp.T=0.f; twp.S0=0.f; twp.S1=0.f; twp.S2=0.f; twp.C0=0.f; twp.C1=0.f; twp.C2=0.f;
    for (int wI = 0; wI < wid; wI++) twp = tsc_comb(twp, s_wt[wI]);
    TSC inclT = tsc_comb(twp, tv);
    if (j == 255) {
        g_cTSC[c*7+0]=inclT.T;
        g_cTSC[c*7+1]=inclT.S0; g_cTSC[c*7+2]=inclT.S1; g_cTSC[c*7+3]=inclT.S2;
        g_cTSC[c*7+4]=inclT.C0; g_cTSC[c*7+5]=inclT.C1; g_cTSC[c*7+6]=inclT.C2;
    }

    // ---- grid barrier 2 ----
    gbar(&g_bar2, NCHT);

    // ---- cross-chunk TSC prefix -> own chunk start state (warp 0) ----
    if (wid == 0) {
        int c0i = b*NCHB + 2*lane, c1i = c0i + 1;
        TSC d0, d1;
        d0.T =__ldcg(&g_cTSC[c0i*7+0]);
        d0.S0=__ldcg(&g_cTSC[c0i*7+1]); d0.S1=__ldcg(&g_cTSC[c0i*7+2]); d0.S2=__ldcg(&g_cTSC[c0i*7+3]);
        d0.C0=__ldcg(&g_cTSC[c0i*7+4]); d0.C1=__ldcg(&g_cTSC[c0i*7+5]); d0.C2=__ldcg(&g_cTSC[c0i*7+6]);
        d1.T =__ldcg(&g_cTSC[c1i*7+0]);
        d1.S0=__ldcg(&g_cTSC[c1i*7+1]); d1.S1=__ldcg(&g_cTSC[c1i*7+2]); d1.S2=__ldcg(&g_cTSC[c1i*7+3]);
        d1.C0=__ldcg(&g_cTSC[c1i*7+4]); d1.C1=__ldcg(&g_cTSC[c1i*7+5]); d1.C2=__ldcg(&g_cTSC[c1i*7+6]);
        TSC pr = tsc_comb(d0, d1);
        #pragma unroll
        for (int off = 1; off < 32; off <<= 1) {
            TSC u = shfl_up_tsc(pr, off);
            if (lane >= off) pr = tsc_comb(u, pr);
        }
        TSC ex = shfl_up_tsc(pr, 1);
        if (lane == 0) { ex.T=0.f; ex.S0=0.f; ex.S1=0.f; ex.S2=0.f; ex.C0=0.f; ex.C1=0.f; ex.C2=0.f; }
        if (lane == pairlane) {
            TSC sel = odd ? tsc_comb(ex, d0) : ex;
            float ip0 = init_pos[b*3+0], ip1 = init_pos[b*3+1], ip2 = init_pos[b*3+2];
            float iv0 = init_vel[b*3+0], iv1 = init_vel[b*3+1], iv2 = init_vel[b*3+2];
            s_start[0] = ip0 + iv0*sel.T + sel.C0;
            s_start[1] = ip1 + iv1*sel.T + sel.C1;
            s_start[2] = ip2 + iv2*sel.T + sel.C2;
            s_start[3] = iv0 + sel.S0;
            s_start[4] = iv1 + sel.S1;
            s_start[5] = iv2 + sel.S2;
        }
    }
    __syncthreads();

    // ---- Phase C: final pos/vel from in-register TSC ----
    {
        float ps0 = s_start[0], ps1 = s_start[1], ps2 = s_start[2];
        float vs0 = s_start[3], vs1 = s_start[4], vs2 = s_start[5];
        float4* o4 = reinterpret_cast<float4*>(out + ob);
        o4[0] = make_float4(ps0 + vs0*inclT.T + inclT.C0,
                            ps1 + vs1*inclT.T + inclT.C1,
                            ps2 + vs2*inclT.T + inclT.C2,
                            vs0 + inclT.S0);
        reinterpret_cast<float2*>(out + ob + 4)[0] =
            make_float2(vs1 + inclT.S1, vs2 + inclT.S2);
    }
}

// ---------------------------------------------------------------------------
extern "C" void kernel_launch(void* const* d_in, const int* in_sizes, int n_in,
                              void* d_out, int out_size)
{
    const float* acc      = (const float*)d_in[0];
    const float* gyro     = (const float*)d_in[1];
    const float* dt       = (const float*)d_in[2];
    const float* init_pos = (const float*)d_in[3];
    const float* init_vel = (const float*)d_in[4];
    const float* init_rot = (const float*)d_in[5];
    const float* W_enc    = (const float*)d_in[6];
    const float* b_enc    = (const float*)d_in[7];
    const float* W_dec    = (const float*)d_in[8];
    const float* b_dec    = (const float*)d_in[9];
    float* out = (float*)d_out;

    mlp_kernel<<<NROWS/128, 64>>>(acc, gyro, dt, W_enc, b_enc, W_dec, b_dec, out);
    fused_kernel<<<NCHT, 256>>>(dt, init_pos, init_vel, init_rot, out);
}